// round 10
// baseline (speedup 1.0000x reference)
#include <cuda_runtime.h>
#include <cstdint>

// Fixed problem shapes
static constexpr int NP     = 128;           // partitions
static constexpr int Cc     = 32;            // key channels
static constexpr int Dd     = 128;           // value/query dim
static constexpr int Bb     = 4;
static constexpr int Ss     = 2048;
static constexpr int Kk     = 2;
static constexpr int NPAIRS = Bb * Ss * Kk;  // 16384
static constexpr int NTOK   = Bb * Ss;       // 8192

static constexpr int NTHR   = 1024;
static constexpr int NBLK   = 2 * NP;        // 256 blocks = (partition, half)
static constexpr int HALFN  = NPAIRS / 2;    // 8192 pairs per half
static constexpr int PER    = HALFN / 4 / NTHR;    // 2 int4 per thread
static constexpr int CAP    = 512;           // absolute match capacity
static constexpr int STAGE  = 96;            // smem-staged rows (mean 64, sigma 8)

// Dynamic smem layout (float4 units then tail):
//   q_sm  [1024]            16384 B
//   red4  [32*33]           16896 B
//   v_sm  [STAGE*32]        49152 B
//   k_sm  [STAGE*32] floats 12288 B
//   js    [CAP] int          2048 B
//   wsum  [32] int            128 B
//   ephase                      4 B
static constexpr int SMEM_BYTES = 16384 + 16896 + 49152 + 12288 + 2048 + 128 + 16;

// Persistent device state.
__device__ float g_P[2 * NP * Dd];           // per-(half,partition) partial rows
__device__ unsigned          g_bar_count = 0;
__device__ volatile unsigned g_bar_phase = 0;  // monotonic across graph replays

__device__ __forceinline__ void cp16(void* dst, const void* src) {
    uint32_t d = (uint32_t)__cvta_generic_to_shared(dst);
    asm volatile("cp.async.ca.shared.global [%0], [%1], 16;"
                 :: "r"(d), "l"(src) : "memory");
}

// ---------------------------------------------------------------------------
// 256 blocks x 1024 threads, 2 CTAs/SM (all co-resident -> spin barrier safe).
//   Entry:   cp.async 16KB q tile (overlaps everything until phase 3).
//   Phase 1: scan half h of idx, two-level shfl scan -> compaction (~64).
//   Stage:   cp.async ALL matched key rows + value rows into smem -> ONE
//            combined DRAM wait (keys/values trips overlapped).
//   Phase 2: per-warp: w = mean(key row) via 5-round butterfly from smem,
//            FMA smem value row; transpose + warp-shfl reduce -> g_P row.
//   -- grid barrier (pre-barrier idx prefetch for phase 3) --
//   Phase 3: out = (P0[i0]+P1[i0]+P0[i1]+P1[i1]) * q_sm, 1 float4/thread.
// ---------------------------------------------------------------------------
__global__ void __launch_bounds__(NTHR, 2) k_fused(
    const int*   __restrict__ idx,
    const float* __restrict__ keys,
    const float* __restrict__ values,
    const float* __restrict__ q,
    float*       __restrict__ out)
{
    extern __shared__ float4 dyn[];
    float4*   q_sm  = dyn;                        // [1024]
    float4*   red4  = q_sm + 1024;                // [32*33] padded transpose
    float4*   v_sm  = red4 + 32 * 33;             // [STAGE*32]
    float*    k_sm  = (float*)(v_sm + STAGE*32);  // [STAGE*32]
    int*      js    = (int*)(k_sm + STAGE*32);    // [CAP]
    int*      wsum  = js + CAP;                   // [32]
    unsigned* ephase = (unsigned*)(wsum + 32);

    const int p    = blockIdx.x >> 1;
    const int h    = blockIdx.x & 1;
    const int tid  = threadIdx.x;
    const int lane = tid & 31;
    const int wid  = tid >> 5;
    const int base = blockIdx.x * NTHR + tid;     // phase-3 float4 index

    // ---- Entry: async-prefetch q tile (in flight until phase 3)
    cp16(&q_sm[tid], (const float4*)q + base);
    asm volatile("cp.async.commit_group;" ::: "memory");

    if (tid == 0) *ephase = g_bar_phase;          // snapshot before any release

    // ---- Phase 1a: strided-coalesced idx load (2 int4/thread), count
    const int4* idx4 = (const int4*)idx + h * (HALFN / 4);
    int4 my[PER];
    int cnt = 0;
    #pragma unroll
    for (int i = 0; i < PER; i++) {
        my[i] = idx4[i * NTHR + tid];
        cnt += (my[i].x == p) + (my[i].y == p) + (my[i].z == p) + (my[i].w == p);
    }

    // ---- Phase 1b: two-level exclusive scan (warp shfl + 32-entry top)
    int inc = cnt;
    #pragma unroll
    for (int o = 1; o < 32; o <<= 1) {
        int v = __shfl_up_sync(0xFFFFFFFFu, inc, o);
        if (lane >= o) inc += v;
    }
    if (lane == 31) wsum[wid] = inc;
    __syncthreads();
    if (wid == 0) {
        int v = wsum[lane];
        #pragma unroll
        for (int o = 1; o < 32; o <<= 1) {
            int u = __shfl_up_sync(0xFFFFFFFFu, v, o);
            if (lane >= o) v += u;
        }
        wsum[lane] = v;                           // inclusive prefix of warp totals
    }
    __syncthreads();
    int n   = wsum[31];
    int pos = (wid ? wsum[wid - 1] : 0) + (inc - cnt);

    // ---- Phase 1c: emit matched pair indices (fixed deterministic order)
    #pragma unroll
    for (int i = 0; i < PER; i++) {
        const int j = h * HALFN + (i * NTHR + tid) * 4;
        if (my[i].x == p && pos < CAP) js[pos++] = j + 0;
        if (my[i].y == p && pos < CAP) js[pos++] = j + 1;
        if (my[i].z == p && pos < CAP) js[pos++] = j + 2;
        if (my[i].w == p && pos < CAP) js[pos++] = j + 3;
    }
    if (n > CAP) n = CAP;
    __syncthreads();

    // ---- Stage: cp.async matched key rows AND value rows together.
    const int nst = (n < STAGE) ? n : STAGE;
    {   // keys: 8 threads x 16B per 128B row; one sweep covers 128 rows
        const int m = tid >> 3, c = tid & 7;
        if (m < nst)
            cp16(k_sm + m * 32 + c * 4, keys + (size_t)js[m] * Cc + c * 4);
    }
    {   // values: 32 threads x 16B per 512B row; 3 sweeps cover 96 rows
        #pragma unroll
        for (int s = 0; s < 3; s++) {
            const int m = s * 32 + wid;
            if (m < nst)
                cp16(v_sm + m * 32 + lane,
                     (const float4*)values + (size_t)(js[m] >> 1) * 32 + lane);
        }
    }
    asm volatile("cp.async.commit_group;" ::: "memory");
    asm volatile("cp.async.wait_group 0;"  ::: "memory");
    __syncthreads();

    // ---- Phase 2: per-warp fused weight+gather from smem.
    {
        float4 acc = make_float4(0.f, 0.f, 0.f, 0.f);
        for (int m = wid; m < n; m += 32) {       // warp-uniform m
            float  k;
            float4 v;
            if (m < STAGE) {                      // staged (normal case)
                k = k_sm[m * 32 + lane];
                v = v_sm[m * 32 + lane];
            } else {                              // overflow fallback: global
                const int j = js[m];
                k = keys[(size_t)j * Cc + lane];
                v = ((const float4*)values)[(size_t)(j >> 1) * 32 + lane];
            }
            #pragma unroll
            for (int o = 16; o >= 1; o >>= 1)
                k += __shfl_xor_sync(0xFFFFFFFFu, k, o);
            const float w = k * (1.0f / Cc);
            acc.x += w * v.x; acc.y += w * v.y;
            acc.z += w * v.z; acc.w += w * v.w;
        }
        red4[wid * 33 + lane] = acc;
        __syncthreads();
        // warp-transpose reduce: warp `wid` owns column d4=wid, lanes=slices
        float4 v = red4[lane * 33 + wid];
        #pragma unroll
        for (int o = 16; o >= 1; o >>= 1) {
            v.x += __shfl_down_sync(0xFFFFFFFFu, v.x, o);
            v.y += __shfl_down_sync(0xFFFFFFFFu, v.y, o);
            v.z += __shfl_down_sync(0xFFFFFFFFu, v.z, o);
            v.w += __shfl_down_sync(0xFFFFFFFFu, v.w, o);
        }
        if (lane == 0)
            ((float4*)g_P)[(h * NP + p) * 32 + wid] = v;
    }

    // ---- Prefetch phase-3 indices (L2-hot) before the barrier
    const int2 ii = ((const int2*)idx)[base >> 5];

    // ---- Grid barrier (256 arrivals; all CTAs co-resident at 2/SM)
    __syncthreads();
    const unsigned tgt = *ephase + 1;
    if (tid == 0) {
        __threadfence();                          // publish g_P
        if (atomicAdd(&g_bar_count, 1u) == NBLK - 1) {
            g_bar_count = 0;
            __threadfence();
            g_bar_phase = tgt;                    // release
        } else {
            while (g_bar_phase < tgt) __nanosleep(32);
        }
    }
    __syncthreads();

    // ---- Phase 3: one float4 per thread; P rows L2-resident, q from smem
    {
        const int d4 = base & 31;
        const float4* P0 = (const float4*)g_P;    // half-0 rows
        const float4* P1 = P0 + NP * (Dd / 4);    // half-1 rows
        float4 a0 = P0[ii.x * 32 + d4];
        float4 b0 = P1[ii.x * 32 + d4];
        float4 a1 = P0[ii.y * 32 + d4];
        float4 b1 = P1[ii.y * 32 + d4];
        float4 qv = q_sm[tid];
        float4 o;
        o.x = ((a0.x + b0.x) + (a1.x + b1.x)) * qv.x;
        o.y = ((a0.y + b0.y) + (a1.y + b1.y)) * qv.y;
        o.z = ((a0.z + b0.z) + (a1.z + b1.z)) * qv.z;
        o.w = ((a0.w + b0.w) + (a1.w + b1.w)) * qv.w;
        ((float4*)out)[base] = o;
    }
}

extern "C" void kernel_launch(void* const* d_in, const int* in_sizes, int n_in,
                              void* d_out, int out_size)
{
    const int*   idx     = (const int*)  d_in[0];  // [B,S,K] int32
    const float* keys    = (const float*)d_in[1];  // [B,S,K,C] f32
    const float* values  = (const float*)d_in[2];  // [B,S,D]   f32
    const float* queries = (const float*)d_in[3];  // [B,S,D]   f32
    float*       out     = (float*)d_out;          // [B,S,D]   f32

    (void)in_sizes; (void)n_in; (void)out_size;

    static bool attr_done = false;
    if (!attr_done) {
        cudaFuncSetAttribute(k_fused, cudaFuncAttributeMaxDynamicSharedMemorySize,
                             SMEM_BYTES);
        attr_done = true;
    }
    k_fused<<<NBLK, NTHR, SMEM_BYTES>>>(idx, keys, values, queries, out);
}